// round 13
// baseline (speedup 1.0000x reference)
#include <cuda_runtime.h>
#include <cuda_bf16.h>
#include <stdint.h>

#define D_DIM    64
#define K_CENT   512
#define BM       128
#define BN       64
#define NTHREADS 128

// SMEM byte offsets (rows are 128 bf16 = 256 B = 16 chunks of 16B)
#define SM_A     0           // 128 x 128 bf16 = 32768
#define SM_B     32768       // 64 x 128 bf16  = 16384
#define SM_C2    49152       // 64 f32
#define SM_BETA  49408       // 64 f32
#define SM_X2    49664       // 128 f32
#define SM_TOTAL 50176
// epilogue staging buffer reuses [0, 36864): 128 rows x 72 floats

// Global images: rows are [hi(64) | lo(64)] bf16
__device__ __align__(16) __nv_bfloat16 g_cbf[K_CENT * 128];      // 128 KB
__device__ __align__(16) __nv_bfloat16 g_ximg[65536 * 128];      // 16 MB (L2-resident)
__device__ float g_c2[K_CENT];
__device__ float g_x2[65536];

// ---------------- helpers ----------------
static __device__ __forceinline__ uint32_t smem_u32(const void* p) {
    uint32_t a;
    asm("{ .reg .u64 t; cvta.to.shared.u64 t, %1; cvt.u32.u64 %0, t; }" : "=r"(a) : "l"(p));
    return a;
}

// XOR swizzle on 16B chunks (16 chunks/row), conflict-free ldmatrix/cp.async
static __device__ __forceinline__ uint32_t sw_off(uint32_t row, uint32_t ch) {
    return ((row << 4) + (ch & 0xFFFFFFF8u) + ((ch & 7u) ^ (row & 7u))) << 4;
}

static __device__ __forceinline__ uint32_t pack_bf2(__nv_bfloat16 a, __nv_bfloat16 b) {
    __nv_bfloat162 t; t.x = a; t.y = b;
    return *reinterpret_cast<uint32_t*>(&t);
}

static __device__ __forceinline__ void ldsm4(uint32_t* r, uint32_t addr) {
    asm volatile("ldmatrix.sync.aligned.m8n8.x4.shared.b16 {%0,%1,%2,%3}, [%4];"
                 : "=r"(r[0]), "=r"(r[1]), "=r"(r[2]), "=r"(r[3]) : "r"(addr));
}

static __device__ __forceinline__ void mma16816(float* c, const uint32_t* a,
                                                uint32_t b0, uint32_t b1) {
    asm volatile(
        "mma.sync.aligned.m16n8k16.row.col.f32.bf16.bf16.f32 "
        "{%0,%1,%2,%3}, {%4,%5,%6,%7}, {%8,%9}, {%0,%1,%2,%3};"
        : "+f"(c[0]), "+f"(c[1]), "+f"(c[2]), "+f"(c[3])
        : "r"(a[0]), "r"(a[1]), "r"(a[2]), "r"(a[3]), "r"(b0), "r"(b1));
}

static __device__ __forceinline__ void cp16(uint32_t dst, const void* src) {
    asm volatile("cp.async.cg.shared.global [%0], [%1], 16;"
                 :: "r"(dst), "l"(src) : "memory");
}

template <int N>
static __device__ __forceinline__ void cpwait() {
    asm volatile("cp.async.wait_group %0;" :: "n"(N) : "memory");
}

// exp(-t), t >= 0, denormal-correct even under fast-math
static __device__ __forceinline__ float exp_neg(float t) {
    float a = -t * 1.4426950408889634f;
    float n = rintf(a);
    float f = a - n;
    float p = exp2f(f);
    return ldexpf(p, (int)n);
}

// ---------------- fused prep: X image (blocks 0..1023) + center image (blocks 1024..1055) ----------------
__global__ void __launch_bounds__(512)
rbf_prep(const float* __restrict__ x, const float* __restrict__ centers) {
    int b = blockIdx.x;
    if (b < 1024) {
        int t = b * 512 + threadIdx.x;
        int row = t >> 3, seg = t & 7;
        const float4* p = reinterpret_cast<const float4*>(x + (size_t)row * D_DIM + seg * 8);
        float4 v0 = p[0], v1 = p[1];
        float f[8] = {v0.x, v0.y, v0.z, v0.w, v1.x, v1.y, v1.z, v1.w};
        uint32_t hv[4], lv[4];
        float s = 0.f;
        #pragma unroll
        for (int j = 0; j < 4; j++) {
            float a = f[2 * j], bb = f[2 * j + 1];
            s += a * a + bb * bb;
            __nv_bfloat16 h0 = __float2bfloat16(a);
            __nv_bfloat16 h1 = __float2bfloat16(bb);
            __nv_bfloat16 l0 = __float2bfloat16(a - __bfloat162float(h0));
            __nv_bfloat16 l1 = __float2bfloat16(bb - __bfloat162float(h1));
            hv[j] = pack_bf2(h0, h1);
            lv[j] = pack_bf2(l0, l1);
        }
        uint4* rowp = reinterpret_cast<uint4*>(g_ximg + (size_t)row * 128);
        rowp[seg]     = make_uint4(hv[0], hv[1], hv[2], hv[3]);
        rowp[8 + seg] = make_uint4(lv[0], lv[1], lv[2], lv[3]);
        s += __shfl_down_sync(0xFFFFFFFFu, s, 4, 8);
        s += __shfl_down_sync(0xFFFFFFFFu, s, 2, 8);
        s += __shfl_down_sync(0xFFFFFFFFu, s, 1, 8);
        if (seg == 0) g_x2[row] = s;
    } else {
        int w = ((b - 1024) * 512 + (int)threadIdx.x) >> 5;
        int lane = threadIdx.x & 31;
        if (w < K_CENT) {
            float2 v = reinterpret_cast<const float2*>(centers + (size_t)w * D_DIM)[lane];
            __nv_bfloat16 h0 = __float2bfloat16(v.x);
            __nv_bfloat16 h1 = __float2bfloat16(v.y);
            __nv_bfloat16 l0 = __float2bfloat16(v.x - __bfloat162float(h0));
            __nv_bfloat16 l1 = __float2bfloat16(v.y - __bfloat162float(h1));
            uint32_t* row = reinterpret_cast<uint32_t*>(g_cbf + (size_t)w * 128);
            row[lane]      = pack_bf2(h0, h1);
            row[32 + lane] = pack_bf2(l0, l1);
            float s = v.x * v.x + v.y * v.y;
            #pragma unroll
            for (int o = 16; o > 0; o >>= 1) s += __shfl_down_sync(0xFFFFFFFFu, s, o);
            if (lane == 0) g_c2[w] = s;
        }
    }
}

// Full kstep (s=0..3): A=xh(s) against B=ch(s) and B=cl(s+4). 8 ldsm, 32 MMAs.
static __device__ __forceinline__ void kstep_full(
    int s, uint32_t sb, float (&acc)[4][4][4],
    uint32_t rowA, uint32_t chA, uint32_t rowB, uint32_t chB
) {
    int s2 = s + 4;
    uint32_t a[4][4], b1[2][4], b2[2][4];
    #pragma unroll
    for (int mi = 0; mi < 4; mi++)
        ldsm4(a[mi], sb + SM_A + sw_off(rowA + mi * 16, 2 * s + chA));
    #pragma unroll
    for (int nq = 0; nq < 2; nq++)
        ldsm4(b1[nq], sb + SM_B + sw_off(rowB + nq * 16, 2 * s + chB));
    #pragma unroll
    for (int nq = 0; nq < 2; nq++)
        ldsm4(b2[nq], sb + SM_B + sw_off(rowB + nq * 16, 2 * s2 + chB));
    #pragma unroll
    for (int mi = 0; mi < 4; mi++)
        #pragma unroll
        for (int ni = 0; ni < 4; ni++)
            mma16816(acc[mi][ni], a[mi], b1[ni >> 1][(ni & 1) * 2],
                     b1[ni >> 1][(ni & 1) * 2 + 1]);
    #pragma unroll
    for (int mi = 0; mi < 4; mi++)
        #pragma unroll
        for (int ni = 0; ni < 4; ni++)
            mma16816(acc[mi][ni], a[mi], b2[ni >> 1][(ni & 1) * 2],
                     b2[ni >> 1][(ni & 1) * 2 + 1]);
}

// Half kstep (s=4..7): A=xl(s) against B=ch(s-4) only (xl*cl dropped). 6 ldsm, 16 MMAs.
static __device__ __forceinline__ void kstep_half(
    int s, uint32_t sb, float (&acc)[4][4][4],
    uint32_t rowA, uint32_t chA, uint32_t rowB, uint32_t chB
) {
    int s2 = s - 4;
    uint32_t a[4][4], b2[2][4];
    #pragma unroll
    for (int mi = 0; mi < 4; mi++)
        ldsm4(a[mi], sb + SM_A + sw_off(rowA + mi * 16, 2 * s + chA));
    #pragma unroll
    for (int nq = 0; nq < 2; nq++)
        ldsm4(b2[nq], sb + SM_B + sw_off(rowB + nq * 16, 2 * s2 + chB));
    #pragma unroll
    for (int mi = 0; mi < 4; mi++)
        #pragma unroll
        for (int ni = 0; ni < 4; ni++)
            mma16816(acc[mi][ni], a[mi], b2[ni >> 1][(ni & 1) * 2],
                     b2[ni >> 1][(ni & 1) * 2 + 1]);
}

// ---------------- main: staged cp.async pipeline + 3-term split + coalesced epilogue ----------------
__global__ void __launch_bounds__(NTHREADS, 4)
rbf_main(const float* __restrict__ betas, float* __restrict__ out) {
    extern __shared__ char smem[];
    uint32_t sb = smem_u32(smem);
    int tid = threadIdx.x;
    int lane = tid & 31;
    int wid = tid >> 5;
    int warp_m = wid & 1;        // 2 warps along M (64 rows each)
    int warp_n = wid >> 1;       // 2 warps along N (32 cols each)
    int m0 = blockIdx.y * BM;
    int n0 = blockIdx.x * BN;

    const char* asrc = reinterpret_cast<const char*>(g_ximg + (size_t)m0 * 128);
    const char* bsrc = reinterpret_cast<const char*>(g_cbf + (size_t)n0 * 128);

    // group 0: all of B (ch+cl both needed from kstep 0) + A quarter 0
    #pragma unroll
    for (int j = 0; j < 8; j++) {                // B: 64 rows x 16 chunks
        int i = j * NTHREADS + tid;
        int r = i >> 4, c = i & 15;
        cp16(sb + SM_B + sw_off(r, c), bsrc + (size_t)r * 256 + c * 16);
    }
    #pragma unroll
    for (int j = 0; j < 4; j++) {                // A q0: 128 rows x chunks 0..3
        int i = j * NTHREADS + tid;
        int r = i >> 2, c = i & 3;
        cp16(sb + SM_A + sw_off(r, c), asrc + (size_t)r * 256 + c * 16);
    }
    asm volatile("cp.async.commit_group;" ::: "memory");

    // groups 1..3: A quarters 1..3
    #pragma unroll
    for (int q = 1; q < 4; q++) {
        #pragma unroll
        for (int j = 0; j < 4; j++) {
            int i = j * NTHREADS + tid;
            int r = i >> 2, c = (q << 2) + (i & 3);
            cp16(sb + SM_A + sw_off(r, c), asrc + (size_t)r * 256 + c * 16);
        }
        asm volatile("cp.async.commit_group;" ::: "memory");
    }

    // scalar tables
    if (tid < BN) {
        reinterpret_cast<float*>(smem + SM_C2)[tid]   = g_c2[n0 + tid];
        reinterpret_cast<float*>(smem + SM_BETA)[tid] = betas[n0 + tid];
    }
    reinterpret_cast<float*>(smem + SM_X2)[tid] = g_x2[m0 + tid];

    uint32_t rowA = warp_m * 64 + (lane & 15);
    uint32_t chA  = (uint32_t)(lane >> 4);
    uint32_t rowB = warp_n * 32 + (lane & 7) + ((lane >> 4) << 3);
    uint32_t chB  = (uint32_t)((lane >> 3) & 1);

    float acc[4][4][4];
    #pragma unroll
    for (int mi = 0; mi < 4; mi++)
        #pragma unroll
        for (int ni = 0; ni < 4; ni++)
            #pragma unroll
            for (int q = 0; q < 4; q++) acc[mi][ni][q] = 0.f;

    // ---- staged mainloop: ksteps 0..3 full (xh), 4..7 half (xl vs ch only) ----
    cpwait<3>(); __syncthreads();
    kstep_full(0, sb, acc, rowA, chA, rowB, chB);
    kstep_full(1, sb, acc, rowA, chA, rowB, chB);
    cpwait<2>(); __syncthreads();
    kstep_full(2, sb, acc, rowA, chA, rowB, chB);
    kstep_full(3, sb, acc, rowA, chA, rowB, chB);
    cpwait<1>(); __syncthreads();
    kstep_half(4, sb, acc, rowA, chA, rowB, chB);
    kstep_half(5, sb, acc, rowA, chA, rowB, chB);
    cpwait<0>(); __syncthreads();
    kstep_half(6, sb, acc, rowA, chA, rowB, chB);
    kstep_half(7, sb, acc, rowA, chA, rowB, chB);

    // ---- epilogue phase 1: d2 -> guarded exp -> smem staging (stride 72 floats) ----
    // Granule stride/row = 36 == 4 (mod 16) -> STS.64 conflict-free per 16-lane phase.
    const float* sx2 = reinterpret_cast<const float*>(smem + SM_X2);
    const float* sc2 = reinterpret_cast<const float*>(smem + SM_C2);
    const float* sbt = reinterpret_cast<const float*>(smem + SM_BETA);
    float* sbuf = reinterpret_cast<float*>(smem);   // reuse A/B region (36864 B < 49152)
    int rbase = warp_m * 64 + (lane >> 2);
    int cbase = warp_n * 32 + (lane & 3) * 2;

    __syncthreads();   // all warps done with mainloop ldsm before overwrite
    #pragma unroll
    for (int mi = 0; mi < 4; mi++) {
        #pragma unroll
        for (int h = 0; h < 2; h++) {
            int row = rbase + mi * 16 + h * 8;
            float x2r = sx2[row];
            #pragma unroll
            for (int ni = 0; ni < 4; ni++) {
                int col = cbase + ni * 8;
                float dot0 = acc[mi][ni][h * 2 + 0];
                float dot1 = acc[mi][ni][h * 2 + 1];
                float d0 = fmaxf(fmaf(-2.f, dot0, x2r + sc2[col]), 0.f);
                float d1 = fmaxf(fmaf(-2.f, dot1, x2r + sc2[col + 1]), 0.f);
                float t0 = sbt[col] * d0;
                float t1 = sbt[col + 1] * d1;
                float e0 = 0.f, e1 = 0.f;
                if (t0 < 104.5f) e0 = exp_neg(t0);
                if (t1 < 104.5f) e1 = exp_neg(t1);
                *reinterpret_cast<float2*>(sbuf + row * 72 + col) = make_float2(e0, e1);
            }
        }
    }
    __syncthreads();

    // ---- phase 2: fully coalesced streaming stores (STG.128, 2 x 256B contiguous/warp-instr) ----
    float* outp = out + (size_t)m0 * K_CENT + n0;
    #pragma unroll
    for (int j = 0; j < 16; j++) {
        int e = j * NTHREADS + tid;
        int row = e >> 4, c4 = e & 15;
        float4 v = *reinterpret_cast<const float4*>(sbuf + row * 72 + c4 * 4);
        __stcs(reinterpret_cast<float4*>(outp + (size_t)row * K_CENT + c4 * 4), v);
    }
}

extern "C" void kernel_launch(void* const* d_in, const int* in_sizes, int n_in,
                              void* d_out, int out_size) {
    const float* x       = (const float*)d_in[0];
    const float* centers = (const float*)d_in[1];
    const float* betas   = (const float*)d_in[2];
    float* out = (float*)d_out;

    int B = in_sizes[0] / D_DIM;   // 65536
    cudaFuncSetAttribute(rbf_main, cudaFuncAttributeMaxDynamicSharedMemorySize, SM_TOTAL);

    rbf_prep<<<(B * 8) / 512 + 32, 512>>>(x, centers);
    dim3 grid(K_CENT / BN, B / BM);   // N fastest: CTAs sharing an A tile are adjacent
    rbf_main<<<grid, NTHREADS, SM_TOTAL>>>(betas, out);
}

// round 14
// speedup vs baseline: 1.2574x; 1.2574x over previous
#include <cuda_runtime.h>
#include <cuda_bf16.h>
#include <stdint.h>

#define D_DIM    64
#define K_CENT   512
#define BM       128
#define BN       64
#define NTHREADS 128
#define MT_TOTAL 512          // 65536 / BM
#define CTA_ROWS 74           // persistent m-stride (grid.y)

// SMEM layout
#define SM_A     0            // 128 x 128 bf16 = 32768
#define SM_B     32768        // 64 x 128 bf16  = 16384
#define SM_C2    49152        // 64 f32
#define SM_BETA  49408        // 64 f32
#define SM_X2    49664        // 2 x 128 f32 (double-buffered)
#define SM_TOTAL 50688

// Global images: rows are [hi(64) | lo(64)] bf16
__device__ __align__(16) __nv_bfloat16 g_cbf[K_CENT * 128];      // 128 KB
__device__ __align__(16) __nv_bfloat16 g_ximg[65536 * 128];      // 16 MB (L2-resident)
__device__ __align__(16) float g_c2[K_CENT];
__device__ __align__(16) float g_x2[65536];

// ---------------- helpers ----------------
static __device__ __forceinline__ uint32_t smem_u32(const void* p) {
    uint32_t a;
    asm("{ .reg .u64 t; cvta.to.shared.u64 t, %1; cvt.u32.u64 %0, t; }" : "=r"(a) : "l"(p));
    return a;
}

// XOR swizzle on 16B chunks (16 chunks/row), conflict-free ldmatrix/cp.async
static __device__ __forceinline__ uint32_t sw_off(uint32_t row, uint32_t ch) {
    return ((row << 4) + (ch & 0xFFFFFFF8u) + ((ch & 7u) ^ (row & 7u))) << 4;
}

static __device__ __forceinline__ uint32_t pack_bf2(__nv_bfloat16 a, __nv_bfloat16 b) {
    __nv_bfloat162 t; t.x = a; t.y = b;
    return *reinterpret_cast<uint32_t*>(&t);
}

static __device__ __forceinline__ void ldsm4(uint32_t* r, uint32_t addr) {
    asm volatile("ldmatrix.sync.aligned.m8n8.x4.shared.b16 {%0,%1,%2,%3}, [%4];"
                 : "=r"(r[0]), "=r"(r[1]), "=r"(r[2]), "=r"(r[3]) : "r"(addr));
}

static __device__ __forceinline__ void mma16816(float* c, const uint32_t* a,
                                                uint32_t b0, uint32_t b1) {
    asm volatile(
        "mma.sync.aligned.m16n8k16.row.col.f32.bf16.bf16.f32 "
        "{%0,%1,%2,%3}, {%4,%5,%6,%7}, {%8,%9}, {%0,%1,%2,%3};"
        : "+f"(c[0]), "+f"(c[1]), "+f"(c[2]), "+f"(c[3])
        : "r"(a[0]), "r"(a[1]), "r"(a[2]), "r"(a[3]), "r"(b0), "r"(b1));
}

static __device__ __forceinline__ void cp16(uint32_t dst, const void* src) {
    asm volatile("cp.async.cg.shared.global [%0], [%1], 16;"
                 :: "r"(dst), "l"(src) : "memory");
}

template <int N>
static __device__ __forceinline__ void cpwait() {
    asm volatile("cp.async.wait_group %0;" :: "n"(N) : "memory");
}

// exp(-t), t >= 0, denormal-correct even under fast-math
static __device__ __forceinline__ float exp_neg(float t) {
    float a = -t * 1.4426950408889634f;
    float n = rintf(a);
    float f = a - n;
    float p = exp2f(f);
    return ldexpf(p, (int)n);
}

// ---------------- fused prep: X image (blocks 0..1023) + center image (blocks 1024..1055) ----------------
__global__ void __launch_bounds__(512)
rbf_prep(const float* __restrict__ x, const float* __restrict__ centers) {
    int b = blockIdx.x;
    if (b < 1024) {
        int t = b * 512 + threadIdx.x;
        int row = t >> 3, seg = t & 7;
        const float4* p = reinterpret_cast<const float4*>(x + (size_t)row * D_DIM + seg * 8);
        float4 v0 = p[0], v1 = p[1];
        float f[8] = {v0.x, v0.y, v0.z, v0.w, v1.x, v1.y, v1.z, v1.w};
        uint32_t hv[4], lv[4];
        float s = 0.f;
        #pragma unroll
        for (int j = 0; j < 4; j++) {
            float a = f[2 * j], bb = f[2 * j + 1];
            s += a * a + bb * bb;
            __nv_bfloat16 h0 = __float2bfloat16(a);
            __nv_bfloat16 h1 = __float2bfloat16(bb);
            __nv_bfloat16 l0 = __float2bfloat16(a - __bfloat162float(h0));
            __nv_bfloat16 l1 = __float2bfloat16(bb - __bfloat162float(h1));
            hv[j] = pack_bf2(h0, h1);
            lv[j] = pack_bf2(l0, l1);
        }
        uint4* rowp = reinterpret_cast<uint4*>(g_ximg + (size_t)row * 128);
        rowp[seg]     = make_uint4(hv[0], hv[1], hv[2], hv[3]);
        rowp[8 + seg] = make_uint4(lv[0], lv[1], lv[2], lv[3]);
        s += __shfl_down_sync(0xFFFFFFFFu, s, 4, 8);
        s += __shfl_down_sync(0xFFFFFFFFu, s, 2, 8);
        s += __shfl_down_sync(0xFFFFFFFFu, s, 1, 8);
        if (seg == 0) g_x2[row] = s;
    } else {
        int w = ((b - 1024) * 512 + (int)threadIdx.x) >> 5;
        int lane = threadIdx.x & 31;
        if (w < K_CENT) {
            float2 v = reinterpret_cast<const float2*>(centers + (size_t)w * D_DIM)[lane];
            __nv_bfloat16 h0 = __float2bfloat16(v.x);
            __nv_bfloat16 h1 = __float2bfloat16(v.y);
            __nv_bfloat16 l0 = __float2bfloat16(v.x - __bfloat162float(h0));
            __nv_bfloat16 l1 = __float2bfloat16(v.y - __bfloat162float(h1));
            uint32_t* row = reinterpret_cast<uint32_t*>(g_cbf + (size_t)w * 128);
            row[lane]      = pack_bf2(h0, h1);
            row[32 + lane] = pack_bf2(l0, l1);
            float s = v.x * v.x + v.y * v.y;
            #pragma unroll
            for (int o = 16; o > 0; o >>= 1) s += __shfl_down_sync(0xFFFFFFFFu, s, o);
            if (lane == 0) g_c2[w] = s;
        }
    }
}

// Full kstep (s=0..3): A=xh(s) against B=ch(s) and B=cl(s+4). 8 ldsm, 32 MMAs.
static __device__ __forceinline__ void kstep_full(
    int s, uint32_t sb, float (&acc)[4][4][4],
    uint32_t rowA, uint32_t chA, uint32_t rowB, uint32_t chB
) {
    int s2 = s + 4;
    uint32_t a[4][4], b1[2][4], b2[2][4];
    #pragma unroll
    for (int mi = 0; mi < 4; mi++)
        ldsm4(a[mi], sb + SM_A + sw_off(rowA + mi * 16, 2 * s + chA));
    #pragma unroll
    for (int nq = 0; nq < 2; nq++)
        ldsm4(b1[nq], sb + SM_B + sw_off(rowB + nq * 16, 2 * s + chB));
    #pragma unroll
    for (int nq = 0; nq < 2; nq++)
        ldsm4(b2[nq], sb + SM_B + sw_off(rowB + nq * 16, 2 * s2 + chB));
    #pragma unroll
    for (int mi = 0; mi < 4; mi++)
        #pragma unroll
        for (int ni = 0; ni < 4; ni++)
            mma16816(acc[mi][ni], a[mi], b1[ni >> 1][(ni & 1) * 2],
                     b1[ni >> 1][(ni & 1) * 2 + 1]);
    #pragma unroll
    for (int mi = 0; mi < 4; mi++)
        #pragma unroll
        for (int ni = 0; ni < 4; ni++)
            mma16816(acc[mi][ni], a[mi], b2[ni >> 1][(ni & 1) * 2],
                     b2[ni >> 1][(ni & 1) * 2 + 1]);
}

// Half kstep (s=4..7): A=xl(s) against B=ch(s-4) only (xl*cl dropped). 6 ldsm, 16 MMAs.
static __device__ __forceinline__ void kstep_half(
    int s, uint32_t sb, float (&acc)[4][4][4],
    uint32_t rowA, uint32_t chA, uint32_t rowB, uint32_t chB
) {
    int s2 = s - 4;
    uint32_t a[4][4], b2[2][4];
    #pragma unroll
    for (int mi = 0; mi < 4; mi++)
        ldsm4(a[mi], sb + SM_A + sw_off(rowA + mi * 16, 2 * s + chA));
    #pragma unroll
    for (int nq = 0; nq < 2; nq++)
        ldsm4(b2[nq], sb + SM_B + sw_off(rowB + nq * 16, 2 * s2 + chB));
    #pragma unroll
    for (int mi = 0; mi < 4; mi++)
        #pragma unroll
        for (int ni = 0; ni < 4; ni++)
            mma16816(acc[mi][ni], a[mi], b2[ni >> 1][(ni & 1) * 2],
                     b2[ni >> 1][(ni & 1) * 2 + 1]);
}

// ---------------- main: persistent CTAs, B resident, A prefetched behind epilogue ----------------
__global__ void __launch_bounds__(NTHREADS, 4)
rbf_main(const float* __restrict__ betas, float* __restrict__ out) {
    extern __shared__ char smem[];
    uint32_t sb = smem_u32(smem);
    int tid = threadIdx.x;
    int lane = tid & 31;
    int wid = tid >> 5;
    int warp_m = wid & 1;        // 2 warps along M (64 rows each)
    int warp_n = wid >> 1;       // 2 warps along N (32 cols each)
    int n0 = blockIdx.x * BN;

    // ---- one-time fill: B tile + first A tile + first x2 slice ----
    int mt = blockIdx.y;
    {
        const char* bsrc = reinterpret_cast<const char*>(g_cbf + (size_t)n0 * 128);
        #pragma unroll
        for (int j = 0; j < 8; j++) {
            int i = j * NTHREADS + tid;
            int r = i >> 4, c = i & 15;
            cp16(sb + SM_B + sw_off(r, c), bsrc + (size_t)r * 256 + c * 16);
        }
        const char* asrc = reinterpret_cast<const char*>(g_ximg) + (size_t)mt * BM * 256;
        #pragma unroll
        for (int j = 0; j < 16; j++) {
            int i = j * NTHREADS + tid;
            int r = i >> 4, c = i & 15;
            cp16(sb + SM_A + sw_off(r, c), asrc + (size_t)r * 256 + c * 16);
        }
        if (tid < 32)
            cp16(sb + SM_X2 + tid * 16,
                 reinterpret_cast<const char*>(g_x2 + (size_t)mt * BM) + tid * 16);
        asm volatile("cp.async.commit_group;" ::: "memory");
    }
    if (tid < BN) {
        reinterpret_cast<float*>(smem + SM_C2)[tid]   = g_c2[n0 + tid];
        reinterpret_cast<float*>(smem + SM_BETA)[tid] = betas[n0 + tid];
    }
    cpwait<0>(); __syncthreads();

    uint32_t rowA = warp_m * 64 + (lane & 15);
    uint32_t chA  = (uint32_t)(lane >> 4);
    uint32_t rowB = warp_n * 32 + (lane & 7) + ((lane >> 4) << 3);
    uint32_t chB  = (uint32_t)((lane >> 3) & 1);

    const float* sc2 = reinterpret_cast<const float*>(smem + SM_C2);
    const float* sbt = reinterpret_cast<const float*>(smem + SM_BETA);
    int rbase = warp_m * 64 + (lane >> 2);
    int cbase = warp_n * 32 + (lane & 3) * 2;

    int par = 0;
    for (;;) {
        int next = mt + CTA_ROWS;

        // ---- mainloop on current A tile ----
        float acc[4][4][4];
        #pragma unroll
        for (int mi = 0; mi < 4; mi++)
            #pragma unroll
            for (int ni = 0; ni < 4; ni++)
                #pragma unroll
                for (int q = 0; q < 4; q++) acc[mi][ni][q] = 0.f;

        kstep_full(0, sb, acc, rowA, chA, rowB, chB);
        kstep_full(1, sb, acc, rowA, chA, rowB, chB);
        kstep_full(2, sb, acc, rowA, chA, rowB, chB);
        kstep_full(3, sb, acc, rowA, chA, rowB, chB);
        kstep_half(4, sb, acc, rowA, chA, rowB, chB);
        kstep_half(5, sb, acc, rowA, chA, rowB, chB);
        kstep_half(6, sb, acc, rowA, chA, rowB, chB);
        kstep_half(7, sb, acc, rowA, chA, rowB, chB);

        __syncthreads();   // all warps done reading A before overwrite

        // ---- prefetch next A + x2 (lands during epilogue) ----
        if (next < MT_TOTAL) {
            const char* asrc = reinterpret_cast<const char*>(g_ximg) + (size_t)next * BM * 256;
            #pragma unroll
            for (int j = 0; j < 16; j++) {
                int i = j * NTHREADS + tid;
                int r = i >> 4, c = i & 15;
                cp16(sb + SM_A + sw_off(r, c), asrc + (size_t)r * 256 + c * 16);
            }
            if (tid < 32)
                cp16(sb + SM_X2 + (par ^ 1) * 512 + tid * 16,
                     reinterpret_cast<const char*>(g_x2 + (size_t)next * BM) + tid * 16);
            asm volatile("cp.async.commit_group;" ::: "memory");
        }

        // ---- epilogue (R12-proven direct streaming stores) ----
        const float* sx2 = reinterpret_cast<const float*>(smem + SM_X2 + par * 512);
        float* outp = out + (size_t)mt * BM * K_CENT + n0;
        #pragma unroll
        for (int mi = 0; mi < 4; mi++) {
            #pragma unroll
            for (int h = 0; h < 2; h++) {
                int row = rbase + mi * 16 + h * 8;
                float x2r = sx2[row];
                float* orow = outp + (size_t)row * K_CENT;
                #pragma unroll
                for (int ni = 0; ni < 4; ni++) {
                    int col = cbase + ni * 8;
                    float dot0 = acc[mi][ni][h * 2 + 0];
                    float dot1 = acc[mi][ni][h * 2 + 1];
                    float d0 = fmaxf(fmaf(-2.f, dot0, x2r + sc2[col]), 0.f);
                    float d1 = fmaxf(fmaf(-2.f, dot1, x2r + sc2[col + 1]), 0.f);
                    float t0 = sbt[col] * d0;
                    float t1 = sbt[col + 1] * d1;
                    float e0 = 0.f, e1 = 0.f;
                    if (t0 < 104.5f) e0 = exp_neg(t0);
                    if (t1 < 104.5f) e1 = exp_neg(t1);
                    __stcs(reinterpret_cast<float2*>(orow + col), make_float2(e0, e1));
                }
            }
        }

        if (next >= MT_TOTAL) break;
        cpwait<0>(); __syncthreads();
        mt = next;
        par ^= 1;
    }
}

extern "C" void kernel_launch(void* const* d_in, const int* in_sizes, int n_in,
                              void* d_out, int out_size) {
    const float* x       = (const float*)d_in[0];
    const float* centers = (const float*)d_in[1];
    const float* betas   = (const float*)d_in[2];
    float* out = (float*)d_out;

    int B = in_sizes[0] / D_DIM;   // 65536
    (void)B;
    cudaFuncSetAttribute(rbf_main, cudaFuncAttributeMaxDynamicSharedMemorySize, SM_TOTAL);

    rbf_prep<<<(65536 * 8) / 512 + 32, 512>>>(x, centers);
    dim3 grid(K_CENT / BN, CTA_ROWS);   // 8 x 74 = 592 persistent CTAs (4/SM)
    rbf_main<<<grid, NTHREADS, SM_TOTAL>>>(betas, out);
}

// round 15
// speedup vs baseline: 1.4250x; 1.1333x over previous
#include <cuda_runtime.h>
#include <cuda_bf16.h>
#include <stdint.h>

#define D_DIM    64
#define K_CENT   512
#define BM       64
#define BN       64
#define NTHREADS 128
#define MT_TOTAL 1024         // 65536 / BM
#define CTA_ROWS 111          // persistent m-stride (grid.y); 8*111=888 CTAs = 6/SM

// SMEM layout
#define SM_A     0            // 64 x 128 bf16 = 16384
#define SM_B     16384        // 64 x 128 bf16 = 16384
#define SM_C2    32768        // 64 f32
#define SM_BETA  33024        // 64 f32
#define SM_X2    33280        // 2 x 64 f32 (double-buffered)
#define SM_TOTAL 33792

// Global images: rows are [hi(64) | lo(64)] bf16
__device__ __align__(16) __nv_bfloat16 g_cbf[K_CENT * 128];      // 128 KB
__device__ __align__(16) __nv_bfloat16 g_ximg[65536 * 128];      // 16 MB (L2-resident)
__device__ __align__(16) float g_c2[K_CENT];
__device__ __align__(16) float g_x2[65536];

// ---------------- helpers ----------------
static __device__ __forceinline__ uint32_t smem_u32(const void* p) {
    uint32_t a;
    asm("{ .reg .u64 t; cvta.to.shared.u64 t, %1; cvt.u32.u64 %0, t; }" : "=r"(a) : "l"(p));
    return a;
}

// XOR swizzle on 16B chunks (16 chunks/row), conflict-free ldmatrix/cp.async
static __device__ __forceinline__ uint32_t sw_off(uint32_t row, uint32_t ch) {
    return ((row << 4) + (ch & 0xFFFFFFF8u) + ((ch & 7u) ^ (row & 7u))) << 4;
}

static __device__ __forceinline__ uint32_t pack_bf2(__nv_bfloat16 a, __nv_bfloat16 b) {
    __nv_bfloat162 t; t.x = a; t.y = b;
    return *reinterpret_cast<uint32_t*>(&t);
}

static __device__ __forceinline__ void ldsm4(uint32_t* r, uint32_t addr) {
    asm volatile("ldmatrix.sync.aligned.m8n8.x4.shared.b16 {%0,%1,%2,%3}, [%4];"
                 : "=r"(r[0]), "=r"(r[1]), "=r"(r[2]), "=r"(r[3]) : "r"(addr));
}

static __device__ __forceinline__ void mma16816(float* c, const uint32_t* a,
                                                uint32_t b0, uint32_t b1) {
    asm volatile(
        "mma.sync.aligned.m16n8k16.row.col.f32.bf16.bf16.f32 "
        "{%0,%1,%2,%3}, {%4,%5,%6,%7}, {%8,%9}, {%0,%1,%2,%3};"
        : "+f"(c[0]), "+f"(c[1]), "+f"(c[2]), "+f"(c[3])
        : "r"(a[0]), "r"(a[1]), "r"(a[2]), "r"(a[3]), "r"(b0), "r"(b1));
}

static __device__ __forceinline__ void cp16(uint32_t dst, const void* src) {
    asm volatile("cp.async.cg.shared.global [%0], [%1], 16;"
                 :: "r"(dst), "l"(src) : "memory");
}

template <int N>
static __device__ __forceinline__ void cpwait() {
    asm volatile("cp.async.wait_group %0;" :: "n"(N) : "memory");
}

// exp(-t), t >= 0, denormal-correct even under fast-math
static __device__ __forceinline__ float exp_neg(float t) {
    float a = -t * 1.4426950408889634f;
    float n = rintf(a);
    float f = a - n;
    float p = exp2f(f);
    return ldexpf(p, (int)n);
}

// ---------------- fused prep: X image (blocks 0..1023) + center image (blocks 1024..1055) ----------------
__global__ void __launch_bounds__(512)
rbf_prep(const float* __restrict__ x, const float* __restrict__ centers) {
    int b = blockIdx.x;
    if (b < 1024) {
        int t = b * 512 + threadIdx.x;
        int row = t >> 3, seg = t & 7;
        const float4* p = reinterpret_cast<const float4*>(x + (size_t)row * D_DIM + seg * 8);
        float4 v0 = p[0], v1 = p[1];
        float f[8] = {v0.x, v0.y, v0.z, v0.w, v1.x, v1.y, v1.z, v1.w};
        uint32_t hv[4], lv[4];
        float s = 0.f;
        #pragma unroll
        for (int j = 0; j < 4; j++) {
            float a = f[2 * j], bb = f[2 * j + 1];
            s += a * a + bb * bb;
            __nv_bfloat16 h0 = __float2bfloat16(a);
            __nv_bfloat16 h1 = __float2bfloat16(bb);
            __nv_bfloat16 l0 = __float2bfloat16(a - __bfloat162float(h0));
            __nv_bfloat16 l1 = __float2bfloat16(bb - __bfloat162float(h1));
            hv[j] = pack_bf2(h0, h1);
            lv[j] = pack_bf2(l0, l1);
        }
        uint4* rowp = reinterpret_cast<uint4*>(g_ximg + (size_t)row * 128);
        rowp[seg]     = make_uint4(hv[0], hv[1], hv[2], hv[3]);
        rowp[8 + seg] = make_uint4(lv[0], lv[1], lv[2], lv[3]);
        s += __shfl_down_sync(0xFFFFFFFFu, s, 4, 8);
        s += __shfl_down_sync(0xFFFFFFFFu, s, 2, 8);
        s += __shfl_down_sync(0xFFFFFFFFu, s, 1, 8);
        if (seg == 0) g_x2[row] = s;
    } else {
        int w = ((b - 1024) * 512 + (int)threadIdx.x) >> 5;
        int lane = threadIdx.x & 31;
        if (w < K_CENT) {
            float2 v = reinterpret_cast<const float2*>(centers + (size_t)w * D_DIM)[lane];
            __nv_bfloat16 h0 = __float2bfloat16(v.x);
            __nv_bfloat16 h1 = __float2bfloat16(v.y);
            __nv_bfloat16 l0 = __float2bfloat16(v.x - __bfloat162float(h0));
            __nv_bfloat16 l1 = __float2bfloat16(v.y - __bfloat162float(h1));
            uint32_t* row = reinterpret_cast<uint32_t*>(g_cbf + (size_t)w * 128);
            row[lane]      = pack_bf2(h0, h1);
            row[32 + lane] = pack_bf2(l0, l1);
            float s = v.x * v.x + v.y * v.y;
            #pragma unroll
            for (int o = 16; o > 0; o >>= 1) s += __shfl_down_sync(0xFFFFFFFFu, s, o);
            if (lane == 0) g_c2[w] = s;
        }
    }
}

// Full kstep (s=0..3): A=xh(s) vs B=ch(s) and B=cl(s+4). 6 ldsm, 16 MMAs (32x32 warp tile).
static __device__ __forceinline__ void kstep_full(
    int s, uint32_t sb, float (&acc)[2][4][4],
    uint32_t rowA, uint32_t chA, uint32_t rowB, uint32_t chB
) {
    int s2 = s + 4;
    uint32_t a[2][4], b1[2][4], b2[2][4];
    #pragma unroll
    for (int mi = 0; mi < 2; mi++)
        ldsm4(a[mi], sb + SM_A + sw_off(rowA + mi * 16, 2 * s + chA));
    #pragma unroll
    for (int nq = 0; nq < 2; nq++)
        ldsm4(b1[nq], sb + SM_B + sw_off(rowB + nq * 16, 2 * s + chB));
    #pragma unroll
    for (int nq = 0; nq < 2; nq++)
        ldsm4(b2[nq], sb + SM_B + sw_off(rowB + nq * 16, 2 * s2 + chB));
    #pragma unroll
    for (int mi = 0; mi < 2; mi++)
        #pragma unroll
        for (int ni = 0; ni < 4; ni++)
            mma16816(acc[mi][ni], a[mi], b1[ni >> 1][(ni & 1) * 2],
                     b1[ni >> 1][(ni & 1) * 2 + 1]);
    #pragma unroll
    for (int mi = 0; mi < 2; mi++)
        #pragma unroll
        for (int ni = 0; ni < 4; ni++)
            mma16816(acc[mi][ni], a[mi], b2[ni >> 1][(ni & 1) * 2],
                     b2[ni >> 1][(ni & 1) * 2 + 1]);
}

// Half kstep (s=4..7): A=xl(s) vs B=ch(s-4) only. 4 ldsm, 8 MMAs.
static __device__ __forceinline__ void kstep_half(
    int s, uint32_t sb, float (&acc)[2][4][4],
    uint32_t rowA, uint32_t chA, uint32_t rowB, uint32_t chB
) {
    int s2 = s - 4;
    uint32_t a[2][4], b2[2][4];
    #pragma unroll
    for (int mi = 0; mi < 2; mi++)
        ldsm4(a[mi], sb + SM_A + sw_off(rowA + mi * 16, 2 * s + chA));
    #pragma unroll
    for (int nq = 0; nq < 2; nq++)
        ldsm4(b2[nq], sb + SM_B + sw_off(rowB + nq * 16, 2 * s2 + chB));
    #pragma unroll
    for (int mi = 0; mi < 2; mi++)
        #pragma unroll
        for (int ni = 0; ni < 4; ni++)
            mma16816(acc[mi][ni], a[mi], b2[ni >> 1][(ni & 1) * 2],
                     b2[ni >> 1][(ni & 1) * 2 + 1]);
}

// ---------------- main: persistent 64x64 CTAs, 6/SM (24 warps), B resident ----------------
__global__ void __launch_bounds__(NTHREADS, 6)
rbf_main(const float* __restrict__ betas, float* __restrict__ out) {
    extern __shared__ char smem[];
    uint32_t sb = smem_u32(smem);
    int tid = threadIdx.x;
    int lane = tid & 31;
    int wid = tid >> 5;
    int warp_m = wid & 1;        // 2 warps along M (32 rows each)
    int warp_n = wid >> 1;       // 2 warps along N (32 cols each)
    int n0 = blockIdx.x * BN;

    // ---- one-time fill: B tile + first A tile + first x2 slice ----
    int mt = blockIdx.y;
    {
        const char* bsrc = reinterpret_cast<const char*>(g_cbf + (size_t)n0 * 128);
        #pragma unroll
        for (int j = 0; j < 8; j++) {
            int i = j * NTHREADS + tid;
            int r = i >> 4, c = i & 15;
            cp16(sb + SM_B + sw_off(r, c), bsrc + (size_t)r * 256 + c * 16);
        }
        const char* asrc = reinterpret_cast<const char*>(g_ximg) + (size_t)mt * BM * 256;
        #pragma unroll
        for (int j = 0; j < 8; j++) {
            int i = j * NTHREADS + tid;
            int r = i >> 4, c = i & 15;
            cp16(sb + SM_A + sw_off(r, c), asrc + (size_t)r * 256 + c * 16);
        }
        if (tid < 16)
            cp16(sb + SM_X2 + tid * 16,
                 reinterpret_cast<const char*>(g_x2 + (size_t)mt * BM) + tid * 16);
        asm volatile("cp.async.commit_group;" ::: "memory");
    }
    if (tid < BN) {
        reinterpret_cast<float*>(smem + SM_C2)[tid]   = g_c2[n0 + tid];
        reinterpret_cast<float*>(smem + SM_BETA)[tid] = betas[n0 + tid];
    }
    cpwait<0>(); __syncthreads();

    uint32_t rowA = warp_m * 32 + (lane & 15);
    uint32_t chA  = (uint32_t)(lane >> 4);
    uint32_t rowB = warp_n * 32 + (lane & 7) + ((lane >> 4) << 3);
    uint32_t chB  = (uint32_t)((lane >> 3) & 1);

    const float* sc2 = reinterpret_cast<const float*>(smem + SM_C2);
    const float* sbt = reinterpret_cast<const float*>(smem + SM_BETA);
    int rbase = warp_m * 32 + (lane >> 2);
    int cbase = warp_n * 32 + (lane & 3) * 2;

    int par = 0;
    for (;;) {
        int next = mt + CTA_ROWS;

        // ---- mainloop on current A tile ----
        float acc[2][4][4];
        #pragma unroll
        for (int mi = 0; mi < 2; mi++)
            #pragma unroll
            for (int ni = 0; ni < 4; ni++)
                #pragma unroll
                for (int q = 0; q < 4; q++) acc[mi][ni][q] = 0.f;

        kstep_full(0, sb, acc, rowA, chA, rowB, chB);
        kstep_full(1, sb, acc, rowA, chA, rowB, chB);
        kstep_full(2, sb, acc, rowA, chA, rowB, chB);
        kstep_full(3, sb, acc, rowA, chA, rowB, chB);
        kstep_half(4, sb, acc, rowA, chA, rowB, chB);
        kstep_half(5, sb, acc, rowA, chA, rowB, chB);
        kstep_half(6, sb, acc, rowA, chA, rowB, chB);
        kstep_half(7, sb, acc, rowA, chA, rowB, chB);

        __syncthreads();   // all warps done reading A before overwrite

        // ---- prefetch next A + x2 (lands during epilogue) ----
        if (next < MT_TOTAL) {
            const char* asrc = reinterpret_cast<const char*>(g_ximg) + (size_t)next * BM * 256;
            #pragma unroll
            for (int j = 0; j < 8; j++) {
                int i = j * NTHREADS + tid;
                int r = i >> 4, c = i & 15;
                cp16(sb + SM_A + sw_off(r, c), asrc + (size_t)r * 256 + c * 16);
            }
            if (tid < 16)
                cp16(sb + SM_X2 + (par ^ 1) * 256 + tid * 16,
                     reinterpret_cast<const char*>(g_x2 + (size_t)next * BM) + tid * 16);
            asm volatile("cp.async.commit_group;" ::: "memory");
        }

        // ---- epilogue (direct streaming stores) ----
        const float* sx2 = reinterpret_cast<const float*>(smem + SM_X2 + par * 256);
        float* outp = out + (size_t)mt * BM * K_CENT + n0;
        #pragma unroll
        for (int mi = 0; mi < 2; mi++) {
            #pragma unroll
            for (int h = 0; h < 2; h++) {
                int row = rbase + mi * 16 + h * 8;
                float x2r = sx2[row];
                float* orow = outp + (size_t)row * K_CENT;
                #pragma unroll
                for (int ni = 0; ni < 4; ni++) {
                    int col = cbase + ni * 8;
                    float dot0 = acc[mi][ni][h * 2 + 0];
                    float dot1 = acc[mi][ni][h * 2 + 1];
                    float d0 = fmaxf(fmaf(-2.f, dot0, x2r + sc2[col]), 0.f);
                    float d1 = fmaxf(fmaf(-2.f, dot1, x2r + sc2[col + 1]), 0.f);
                    float t0 = sbt[col] * d0;
                    float t1 = sbt[col + 1] * d1;
                    float e0 = 0.f, e1 = 0.f;
                    if (t0 < 104.5f) e0 = exp_neg(t0);
                    if (t1 < 104.5f) e1 = exp_neg(t1);
                    __stcs(reinterpret_cast<float2*>(orow + col), make_float2(e0, e1));
                }
            }
        }

        if (next >= MT_TOTAL) break;
        cpwait<0>(); __syncthreads();
        mt = next;
        par ^= 1;
    }
}

extern "C" void kernel_launch(void* const* d_in, const int* in_sizes, int n_in,
                              void* d_out, int out_size) {
    const float* x       = (const float*)d_in[0];
    const float* centers = (const float*)d_in[1];
    const float* betas   = (const float*)d_in[2];
    float* out = (float*)d_out;

    int B = in_sizes[0] / D_DIM;   // 65536
    (void)B;
    cudaFuncSetAttribute(rbf_main, cudaFuncAttributeMaxDynamicSharedMemorySize, SM_TOTAL);

    rbf_prep<<<(65536 * 8) / 512 + 32, 512>>>(x, centers);
    dim3 grid(K_CENT / BN, CTA_ROWS);   // 8 x 111 = 888 persistent CTAs (6/SM)
    rbf_main<<<grid, NTHREADS, SM_TOTAL>>>(betas, out);
}

// round 16
// speedup vs baseline: 1.6432x; 1.1532x over previous
#include <cuda_runtime.h>
#include <cuda_bf16.h>
#include <stdint.h>

#define D_DIM    64
#define K_CENT   512
#define BM       64
#define BN       64
#define NTHREADS 128
#define MT_TOTAL 1024         // 65536 / BM
#define CTA_ROWS 111          // persistent m-stride (grid.y); 8*111=888 CTAs = 6/SM

// SMEM layout
#define SM_A     0            // 64 x 128 bf16 = 16384
#define SM_B     16384        // 64 x 128 bf16 = 16384
#define SM_C2    32768        // 64 f32
#define SM_BETA  33024        // 64 f32
#define SM_X2    33280        // 2 x 64 f32 (double-buffered)
#define SM_TOTAL 33792

// Global images: rows are [hi(64) | lo(64)] bf16
__device__ __align__(16) __nv_bfloat16 g_cbf[K_CENT * 128];      // 128 KB
__device__ __align__(16) __nv_bfloat16 g_ximg[65536 * 128];      // 16 MB (L2-resident)
__device__ __align__(16) float g_c2[K_CENT];
__device__ __align__(16) float g_x2[65536];

// ---------------- helpers ----------------
static __device__ __forceinline__ uint32_t smem_u32(const void* p) {
    uint32_t a;
    asm("{ .reg .u64 t; cvta.to.shared.u64 t, %1; cvt.u32.u64 %0, t; }" : "=r"(a) : "l"(p));
    return a;
}

// XOR swizzle on 16B chunks (16 chunks/row), conflict-free ldmatrix/cp.async
static __device__ __forceinline__ uint32_t sw_off(uint32_t row, uint32_t ch) {
    return ((row << 4) + (ch & 0xFFFFFFF8u) + ((ch & 7u) ^ (row & 7u))) << 4;
}

static __device__ __forceinline__ uint32_t pack_bf2(__nv_bfloat16 a, __nv_bfloat16 b) {
    __nv_bfloat162 t; t.x = a; t.y = b;
    return *reinterpret_cast<uint32_t*>(&t);
}

static __device__ __forceinline__ void ldsm4(uint32_t* r, uint32_t addr) {
    asm volatile("ldmatrix.sync.aligned.m8n8.x4.shared.b16 {%0,%1,%2,%3}, [%4];"
                 : "=r"(r[0]), "=r"(r[1]), "=r"(r[2]), "=r"(r[3]) : "r"(addr));
}

static __device__ __forceinline__ void mma16816(float* c, const uint32_t* a,
                                                uint32_t b0, uint32_t b1) {
    asm volatile(
        "mma.sync.aligned.m16n8k16.row.col.f32.bf16.bf16.f32 "
        "{%0,%1,%2,%3}, {%4,%5,%6,%7}, {%8,%9}, {%0,%1,%2,%3};"
        : "+f"(c[0]), "+f"(c[1]), "+f"(c[2]), "+f"(c[3])
        : "r"(a[0]), "r"(a[1]), "r"(a[2]), "r"(a[3]), "r"(b0), "r"(b1));
}

static __device__ __forceinline__ void cp16(uint32_t dst, const void* src) {
    asm volatile("cp.async.cg.shared.global [%0], [%1], 16;"
                 :: "r"(dst), "l"(src) : "memory");
}

template <int N>
static __device__ __forceinline__ void cpwait() {
    asm volatile("cp.async.wait_group %0;" :: "n"(N) : "memory");
}

// exp(-t), t >= 0, denormal-correct even under fast-math
static __device__ __forceinline__ float exp_neg(float t) {
    float a = -t * 1.4426950408889634f;
    float n = rintf(a);
    float f = a - n;
    float p = exp2f(f);
    return ldexpf(p, (int)n);
}

// ---------------- fused prep: X image (blocks 0..1023) + center image (blocks 1024..1055) ----------------
__global__ void __launch_bounds__(512)
rbf_prep(const float* __restrict__ x, const float* __restrict__ centers) {
    int b = blockIdx.x;
    if (b < 1024) {
        int t = b * 512 + threadIdx.x;
        int row = t >> 3, seg = t & 7;
        const float4* p = reinterpret_cast<const float4*>(x + (size_t)row * D_DIM + seg * 8);
        float4 v0 = p[0], v1 = p[1];
        float f[8] = {v0.x, v0.y, v0.z, v0.w, v1.x, v1.y, v1.z, v1.w};
        uint32_t hv[4], lv[4];
        float s = 0.f;
        #pragma unroll
        for (int j = 0; j < 4; j++) {
            float a = f[2 * j], bb = f[2 * j + 1];
            s += a * a + bb * bb;
            __nv_bfloat16 h0 = __float2bfloat16(a);
            __nv_bfloat16 h1 = __float2bfloat16(bb);
            __nv_bfloat16 l0 = __float2bfloat16(a - __bfloat162float(h0));
            __nv_bfloat16 l1 = __float2bfloat16(bb - __bfloat162float(h1));
            hv[j] = pack_bf2(h0, h1);
            lv[j] = pack_bf2(l0, l1);
        }
        uint4* rowp = reinterpret_cast<uint4*>(g_ximg + (size_t)row * 128);
        rowp[seg]     = make_uint4(hv[0], hv[1], hv[2], hv[3]);
        rowp[8 + seg] = make_uint4(lv[0], lv[1], lv[2], lv[3]);
        s += __shfl_down_sync(0xFFFFFFFFu, s, 4, 8);
        s += __shfl_down_sync(0xFFFFFFFFu, s, 2, 8);
        s += __shfl_down_sync(0xFFFFFFFFu, s, 1, 8);
        if (seg == 0) g_x2[row] = s;
    } else {
        int w = ((b - 1024) * 512 + (int)threadIdx.x) >> 5;
        int lane = threadIdx.x & 31;
        if (w < K_CENT) {
            float2 v = reinterpret_cast<const float2*>(centers + (size_t)w * D_DIM)[lane];
            __nv_bfloat16 h0 = __float2bfloat16(v.x);
            __nv_bfloat16 h1 = __float2bfloat16(v.y);
            __nv_bfloat16 l0 = __float2bfloat16(v.x - __bfloat162float(h0));
            __nv_bfloat16 l1 = __float2bfloat16(v.y - __bfloat162float(h1));
            uint32_t* row = reinterpret_cast<uint32_t*>(g_cbf + (size_t)w * 128);
            row[lane]      = pack_bf2(h0, h1);
            row[32 + lane] = pack_bf2(l0, l1);
            float s = v.x * v.x + v.y * v.y;
            #pragma unroll
            for (int o = 16; o > 0; o >>= 1) s += __shfl_down_sync(0xFFFFFFFFu, s, o);
            if (lane == 0) g_c2[w] = s;
        }
    }
}

// Paired kstep s (0..3): computes xh(s)·ch(s) + xl(s)·ch(s) + xh(s)·cl(s)
// with ch loaded ONCE. 8 ldsm, 24 MMAs. Peak live fragments: ah+bh+al = 24 regs.
static __device__ __forceinline__ void kstep_pair(
    int s, uint32_t sb, float (&acc)[2][4][4],
    uint32_t rowA, uint32_t chA, uint32_t rowB, uint32_t chB
) {
    int sl = s + 4;                                  // lo-half chunk index
    uint32_t ah[2][4], bh[2][4];
    #pragma unroll
    for (int mi = 0; mi < 2; mi++)
        ldsm4(ah[mi], sb + SM_A + sw_off(rowA + mi * 16, 2 * s + chA));
    #pragma unroll
    for (int nq = 0; nq < 2; nq++)
        ldsm4(bh[nq], sb + SM_B + sw_off(rowB + nq * 16, 2 * s + chB));
    #pragma unroll
    for (int mi = 0; mi < 2; mi++)
        #pragma unroll
        for (int ni = 0; ni < 4; ni++)
            mma16816(acc[mi][ni], ah[mi], bh[ni >> 1][(ni & 1) * 2],
                     bh[ni >> 1][(ni & 1) * 2 + 1]);
    {   // xl · ch  (ch dies after this)
        uint32_t al[2][4];
        #pragma unroll
        for (int mi = 0; mi < 2; mi++)
            ldsm4(al[mi], sb + SM_A + sw_off(rowA + mi * 16, 2 * sl + chA));
        #pragma unroll
        for (int mi = 0; mi < 2; mi++)
            #pragma unroll
            for (int ni = 0; ni < 4; ni++)
                mma16816(acc[mi][ni], al[mi], bh[ni >> 1][(ni & 1) * 2],
                         bh[ni >> 1][(ni & 1) * 2 + 1]);
    }
    {   // xh · cl
        uint32_t bl[2][4];
        #pragma unroll
        for (int nq = 0; nq < 2; nq++)
            ldsm4(bl[nq], sb + SM_B + sw_off(rowB + nq * 16, 2 * sl + chB));
        #pragma unroll
        for (int mi = 0; mi < 2; mi++)
            #pragma unroll
            for (int ni = 0; ni < 4; ni++)
                mma16816(acc[mi][ni], ah[mi], bl[ni >> 1][(ni & 1) * 2],
                         bl[ni >> 1][(ni & 1) * 2 + 1]);
    }
}

// ---------------- main: persistent 64x64 CTAs, 6/SM (24 warps), B resident ----------------
__global__ void __launch_bounds__(NTHREADS, 6)
rbf_main(const float* __restrict__ betas, float* __restrict__ out) {
    extern __shared__ char smem[];
    uint32_t sb = smem_u32(smem);
    int tid = threadIdx.x;
    int lane = tid & 31;
    int wid = tid >> 5;
    int warp_m = wid & 1;        // 2 warps along M (32 rows each)
    int warp_n = wid >> 1;       // 2 warps along N (32 cols each)
    int n0 = blockIdx.x * BN;

    // ---- one-time fill: B tile + first A tile + first x2 slice ----
    int mt = blockIdx.y;
    {
        const char* bsrc = reinterpret_cast<const char*>(g_cbf + (size_t)n0 * 128);
        #pragma unroll
        for (int j = 0; j < 8; j++) {
            int i = j * NTHREADS + tid;
            int r = i >> 4, c = i & 15;
            cp16(sb + SM_B + sw_off(r, c), bsrc + (size_t)r * 256 + c * 16);
        }
        const char* asrc = reinterpret_cast<const char*>(g_ximg) + (size_t)mt * BM * 256;
        #pragma unroll
        for (int j = 0; j < 8; j++) {
            int i = j * NTHREADS + tid;
            int r = i >> 4, c = i & 15;
            cp16(sb + SM_A + sw_off(r, c), asrc + (size_t)r * 256 + c * 16);
        }
        if (tid < 16)
            cp16(sb + SM_X2 + tid * 16,
                 reinterpret_cast<const char*>(g_x2 + (size_t)mt * BM) + tid * 16);
        asm volatile("cp.async.commit_group;" ::: "memory");
    }
    if (tid < BN) {
        reinterpret_cast<float*>(smem + SM_C2)[tid]   = g_c2[n0 + tid];
        reinterpret_cast<float*>(smem + SM_BETA)[tid] = betas[n0 + tid];
    }
    cpwait<0>(); __syncthreads();

    uint32_t rowA = warp_m * 32 + (lane & 15);
    uint32_t chA  = (uint32_t)(lane >> 4);
    uint32_t rowB = warp_n * 32 + (lane & 7) + ((lane >> 4) << 3);
    uint32_t chB  = (uint32_t)((lane >> 3) & 1);

    const float* sc2 = reinterpret_cast<const float*>(smem + SM_C2);
    const float* sbt = reinterpret_cast<const float*>(smem + SM_BETA);
    int rbase = warp_m * 32 + (lane >> 2);
    int cbase = warp_n * 32 + (lane & 3) * 2;

    int par = 0;
    for (;;) {
        int next = mt + CTA_ROWS;

        // ---- mainloop on current A tile: 4 paired ksteps ----
        float acc[2][4][4];
        #pragma unroll
        for (int mi = 0; mi < 2; mi++)
            #pragma unroll
            for (int ni = 0; ni < 4; ni++)
                #pragma unroll
                for (int q = 0; q < 4; q++) acc[mi][ni][q] = 0.f;

        kstep_pair(0, sb, acc, rowA, chA, rowB, chB);
        kstep_pair(1, sb, acc, rowA, chA, rowB, chB);
        kstep_pair(2, sb, acc, rowA, chA, rowB, chB);
        kstep_pair(3, sb, acc, rowA, chA, rowB, chB);

        __syncthreads();   // all warps done reading A before overwrite

        // ---- prefetch next A + x2 (lands during epilogue) ----
        if (next < MT_TOTAL) {
            const char* asrc = reinterpret_cast<const char*>(g_ximg) + (size_t)next * BM * 256;
            #pragma unroll
            for (int j = 0; j < 8; j++) {
                int i = j * NTHREADS + tid;
                int r = i >> 4, c = i & 15;
                cp16(sb + SM_A + sw_off(r, c), asrc + (size_t)r * 256 + c * 16);
            }
            if (tid < 16)
                cp16(sb + SM_X2 + (par ^ 1) * 256 + tid * 16,
                     reinterpret_cast<const char*>(g_x2 + (size_t)next * BM) + tid * 16);
            asm volatile("cp.async.commit_group;" ::: "memory");
        }

        // ---- epilogue (direct streaming stores) ----
        const float* sx2 = reinterpret_cast<const float*>(smem + SM_X2 + par * 256);
        float* outp = out + (size_t)mt * BM * K_CENT + n0;
        #pragma unroll
        for (int mi = 0; mi < 2; mi++) {
            #pragma unroll
            for (int h = 0; h < 2; h++) {
                int row = rbase + mi * 16 + h * 8;
                float x2r = sx2[row];
                float* orow = outp + (size_t)row * K_CENT;
                #pragma unroll
                for (int ni = 0; ni < 4; ni++) {
                    int col = cbase + ni * 8;
                    float dot0 = acc[mi][ni][h * 2 + 0];
                    float dot1 = acc[mi][ni][h * 2 + 1];
                    float d0 = fmaxf(fmaf(-2.f, dot0, x2r + sc2[col]), 0.f);
                    float d1 = fmaxf(fmaf(-2.f, dot1, x2r + sc2[col + 1]), 0.f);
                    float t0 = sbt[col] * d0;
                    float t1 = sbt[col + 1] * d1;
                    float e0 = 0.f, e1 = 0.f;
                    if (t0 < 104.5f) e0 = exp_neg(t0);
                    if (t1 < 104.5f) e1 = exp_neg(t1);
                    __stcs(reinterpret_cast<float2*>(orow + col), make_float2(e0, e1));
                }
            }
        }

        if (next >= MT_TOTAL) break;
        cpwait<0>(); __syncthreads();
        mt = next;
        par ^= 1;
    }
}

extern "C" void kernel_launch(void* const* d_in, const int* in_sizes, int n_in,
                              void* d_out, int out_size) {
    const float* x       = (const float*)d_in[0];
    const float* centers = (const float*)d_in[1];
    const float* betas   = (const float*)d_in[2];
    float* out = (float*)d_out;

    int B = in_sizes[0] / D_DIM;   // 65536
    (void)B;
    cudaFuncSetAttribute(rbf_main, cudaFuncAttributeMaxDynamicSharedMemorySize, SM_TOTAL);

    rbf_prep<<<(65536 * 8) / 512 + 32, 512>>>(x, centers);
    dim3 grid(K_CENT / BN, CTA_ROWS);   // 8 x 111 = 888 persistent CTAs (6/SM)
    rbf_main<<<grid, NTHREADS, SM_TOTAL>>>(betas, out);
}